// round 12
// baseline (speedup 1.0000x reference)
#include <cuda_runtime.h>
#include <cuda_bf16.h>

#define NH  4096
#define DIN 4096
#define NBLOCKS 888   // 148 SMs x 6 resident blocks (44 regs, 224 thr)

// Persistent-block GEMV with dynamic ticket scheduling.
// Each grabbed ticket j is one LSTM output index; the 7-warp body is identical
// to the proven 74.8us kernel:
//   w0: Wih[j]      . x     w1: Whh[j]      . h      (i gate)
//   w2: Wih[nh+j]   . x     w3: Whh[nh+j]   . h      (f gate)
//   w4: Wih[2nh+j]  . x     w5: Whh[2nh+j]  . h      (g gate)
//   w6: Whh[3nh+j]  . h                              (o gate; x-part REUSES w4,
//                                                     reference sets Wio = Wig slice)
// Dynamic grabbing staggers block finishes -> removes the 61%-full last wave
// (4096/888 = 4.61 waves) without touching the memory-proven loop body.

__device__ int g_ticket = 0;   // reset to 0 by the trailing reset kernel each replay

__global__ void lstm_reset_kernel() { g_ticket = 0; }

__global__ __launch_bounds__(224)
void lstm_cell_kernel(const float* __restrict__ x,
                      const float* __restrict__ h,
                      const float* __restrict__ c,
                      const float* __restrict__ Wih,
                      const float* __restrict__ Whh,
                      const float* __restrict__ bih,
                      const float* __restrict__ bhh,
                      float* __restrict__ out)
{
    const int wid  = threadIdx.x >> 5;
    const int lane = threadIdx.x & 31;

    __shared__ float partial[7];
    __shared__ int   s_j;

    // Branchless per-warp dot-product selection.
    const int use_h_tab[7] = {0, 1, 0, 1, 0, 1, 1};
    const int gate_tab [7] = {0, 0, 1, 1, 2, 2, 3};
    const int use_h = use_h_tab[wid];
    const int gate  = gate_tab[wid];

    const float* W = use_h ? Whh : Wih;
    const float* v = use_h ? h   : x;

    const float4* __restrict__ vr = reinterpret_cast<const float4*>(v);

    while (true) {
        if (threadIdx.x == 0) s_j = atomicAdd(&g_ticket, 1);
        __syncthreads();
        const int j = s_j;
        if (j >= NH) break;

        const long row = (long)gate * NH + j;
        const float4* __restrict__ Wr =
            reinterpret_cast<const float4*>(W + row * (long)DIN);

        // 1024 float4 per row / 32 lanes = 32 float4 per lane.
        // Weights read-once -> __ldcs (evict-first) keeps x/h L2-resident.
        float a0 = 0.f, a1 = 0.f, a2 = 0.f, a3 = 0.f;
        #pragma unroll
        for (int it = 0; it < 8; ++it) {
            const int base = it * 128 + lane;
            float4 w0 = __ldcs(&Wr[base]);        float4 x0 = vr[base];
            float4 w1 = __ldcs(&Wr[base + 32]);   float4 x1 = vr[base + 32];
            float4 w2 = __ldcs(&Wr[base + 64]);   float4 x2 = vr[base + 64];
            float4 w3 = __ldcs(&Wr[base + 96]);   float4 x3 = vr[base + 96];
            a0 += w0.x*x0.x + w0.y*x0.y + w0.z*x0.z + w0.w*x0.w;
            a1 += w1.x*x1.x + w1.y*x1.y + w1.z*x1.z + w1.w*x1.w;
            a2 += w2.x*x2.x + w2.y*x2.y + w2.z*x2.z + w2.w*x2.w;
            a3 += w3.x*x3.x + w3.y*x3.y + w3.z*x3.z + w3.w*x3.w;
        }
        float acc = (a0 + a1) + (a2 + a3);

        // Warp tree-reduce.
        #pragma unroll
        for (int off = 16; off > 0; off >>= 1)
            acc += __shfl_down_sync(0xffffffffu, acc, off);

        if (lane == 0) partial[wid] = acc;
        __syncthreads();

        if (threadIdx.x == 0) {
            const float ai = partial[0] + partial[1] + __ldg(&bih[j])        + __ldg(&bhh[j]);
            const float af = partial[2] + partial[3] + __ldg(&bih[NH + j])   + __ldg(&bhh[NH + j]);
            const float ag = partial[4] + partial[5] + __ldg(&bih[2*NH + j]) + __ldg(&bhh[2*NH + j]);
            // o gate: x-part = g gate's x-dot (reference's Wio slice aliases Wig)
            const float ao = partial[4] + partial[6] + __ldg(&bih[3*NH + j]) + __ldg(&bhh[3*NH + j]);

            const float it_ = 1.f / (1.f + __expf(-ai));
            const float ft_ = 1.f / (1.f + __expf(-af));
            const float gt_ = tanhf(ag);
            const float ot_ = 1.f / (1.f + __expf(-ao));
            const float ct_ = ft_ * __ldg(&c[j]) + it_ * gt_;
            const float ht_ = ot_ * tanhf(ct_);

            out[j         ] = it_;
            out[NH   + j  ] = ft_;
            out[2*NH + j  ] = gt_;
            out[3*NH + j  ] = ot_;
            out[4*NH + j  ] = ct_;
            out[5*NH + j  ] = ht_;
        }
        __syncthreads();   // protect s_j/partial before next grab
    }
}

extern "C" void kernel_launch(void* const* d_in, const int* in_sizes, int n_in,
                              void* d_out, int out_size)
{
    const float* x   = (const float*)d_in[0];
    const float* h   = (const float*)d_in[1];
    const float* c   = (const float*)d_in[2];
    const float* Wih = (const float*)d_in[3];
    const float* Whh = (const float*)d_in[4];
    const float* bih = (const float*)d_in[5];
    const float* bhh = (const float*)d_in[6];
    float* out = (float*)d_out;

    lstm_cell_kernel<<<NBLOCKS, 224>>>(x, h, c, Wih, Whh, bih, bhh, out);
    lstm_reset_kernel<<<1, 1>>>();   // stream-ordered: zero ticket for next replay
}

// round 14
// speedup vs baseline: 1.0180x; 1.0180x over previous
#include <cuda_runtime.h>
#include <cuda_bf16.h>

#define NH  4096
#define DIN 4096
#define NBLOCKS 888   // 148 SMs x 6 resident blocks (44 regs, 224 thr)

// Persistent-block GEMV with dynamic ticket scheduling + in-kernel ticket reset.
// Per-ticket body identical to the proven 74.8us kernel:
//   w0: Wih[j]      . x     w1: Whh[j]      . h      (i gate)
//   w2: Wih[nh+j]   . x     w3: Whh[nh+j]   . h      (f gate)
//   w4: Wih[2nh+j]  . x     w5: Whh[2nh+j]  . h      (g gate)
//   w6: Whh[3nh+j]  . h                              (o gate; x-part REUSES w4,
//                                                     reference sets Wio = Wig slice)
// Dynamic grabbing staggers block finishes (kills the 61%-full last wave of the
// static 4.61-wave schedule; R12 measured the persistent kernel at ~73.9us).
// The LAST block to finish resets the ticket for the next graph replay: a block
// bumps g_done only after its final g_ticket read, so the reset can never race
// a live reader. Single kernel node -> no 4us reset-kernel overhead (R12's bug).

__device__ int g_ticket = 0;
__device__ int g_done   = 0;

__global__ __launch_bounds__(224)
void lstm_cell_kernel(const float* __restrict__ x,
                      const float* __restrict__ h,
                      const float* __restrict__ c,
                      const float* __restrict__ Wih,
                      const float* __restrict__ Whh,
                      const float* __restrict__ bih,
                      const float* __restrict__ bhh,
                      float* __restrict__ out)
{
    const int wid  = threadIdx.x >> 5;
    const int lane = threadIdx.x & 31;

    __shared__ float partial[7];
    __shared__ int   s_j;

    // Branchless per-warp dot-product selection.
    const int use_h_tab[7] = {0, 1, 0, 1, 0, 1, 1};
    const int gate_tab [7] = {0, 0, 1, 1, 2, 2, 3};
    const int use_h = use_h_tab[wid];
    const int gate  = gate_tab[wid];

    const float* W = use_h ? Whh : Wih;
    const float* v = use_h ? h   : x;

    const float4* __restrict__ vr = reinterpret_cast<const float4*>(v);

    while (true) {
        if (threadIdx.x == 0) s_j = atomicAdd(&g_ticket, 1);
        __syncthreads();
        const int j = s_j;
        if (j >= NH) break;

        const long row = (long)gate * NH + j;
        const float4* __restrict__ Wr =
            reinterpret_cast<const float4*>(W + row * (long)DIN);

        // 1024 float4 per row / 32 lanes = 32 float4 per lane.
        // Weights read-once -> __ldcs (evict-first) keeps x/h L2-resident.
        float a0 = 0.f, a1 = 0.f, a2 = 0.f, a3 = 0.f;
        #pragma unroll
        for (int it = 0; it < 8; ++it) {
            const int base = it * 128 + lane;
            float4 w0 = __ldcs(&Wr[base]);        float4 x0 = vr[base];
            float4 w1 = __ldcs(&Wr[base + 32]);   float4 x1 = vr[base + 32];
            float4 w2 = __ldcs(&Wr[base + 64]);   float4 x2 = vr[base + 64];
            float4 w3 = __ldcs(&Wr[base + 96]);   float4 x3 = vr[base + 96];
            a0 += w0.x*x0.x + w0.y*x0.y + w0.z*x0.z + w0.w*x0.w;
            a1 += w1.x*x1.x + w1.y*x1.y + w1.z*x1.z + w1.w*x1.w;
            a2 += w2.x*x2.x + w2.y*x2.y + w2.z*x2.z + w2.w*x2.w;
            a3 += w3.x*x3.x + w3.y*x3.y + w3.z*x3.z + w3.w*x3.w;
        }
        float acc = (a0 + a1) + (a2 + a3);

        // Warp tree-reduce.
        #pragma unroll
        for (int off = 16; off > 0; off >>= 1)
            acc += __shfl_down_sync(0xffffffffu, acc, off);

        if (lane == 0) partial[wid] = acc;
        __syncthreads();

        if (threadIdx.x == 0) {
            const float ai = partial[0] + partial[1] + __ldg(&bih[j])        + __ldg(&bhh[j]);
            const float af = partial[2] + partial[3] + __ldg(&bih[NH + j])   + __ldg(&bhh[NH + j]);
            const float ag = partial[4] + partial[5] + __ldg(&bih[2*NH + j]) + __ldg(&bhh[2*NH + j]);
            // o gate: x-part = g gate's x-dot (reference's Wio slice aliases Wig)
            const float ao = partial[4] + partial[6] + __ldg(&bih[3*NH + j]) + __ldg(&bhh[3*NH + j]);

            const float it_ = 1.f / (1.f + __expf(-ai));
            const float ft_ = 1.f / (1.f + __expf(-af));
            const float gt_ = tanhf(ag);
            const float ot_ = 1.f / (1.f + __expf(-ao));
            const float ct_ = ft_ * __ldg(&c[j]) + it_ * gt_;
            const float ht_ = ot_ * tanhf(ct_);

            out[j         ] = it_;
            out[NH   + j  ] = ft_;
            out[2*NH + j  ] = gt_;
            out[3*NH + j  ] = ot_;
            out[4*NH + j  ] = ct_;
            out[5*NH + j  ] = ht_;
        }
        __syncthreads();   // protect s_j/partial before next grab
    }

    // In-kernel ticket reset: last-finishing block zeroes state for next replay.
    // Safe: every block's final g_ticket read happens-before its g_done bump.
    if (threadIdx.x == 0) {
        __threadfence();
        const int d = atomicAdd(&g_done, 1);
        if (d == NBLOCKS - 1) {
            atomicExch(&g_ticket, 0);
            atomicExch(&g_done, 0);
            __threadfence();
        }
    }
}

extern "C" void kernel_launch(void* const* d_in, const int* in_sizes, int n_in,
                              void* d_out, int out_size)
{
    const float* x   = (const float*)d_in[0];
    const float* h   = (const float*)d_in[1];
    const float* c   = (const float*)d_in[2];
    const float* Wih = (const float*)d_in[3];
    const float* Whh = (const float*)d_in[4];
    const float* bih = (const float*)d_in[5];
    const float* bhh = (const float*)d_in[6];
    float* out = (float*)d_out;

    lstm_cell_kernel<<<NBLOCKS, 224>>>(x, h, c, Wih, Whh, bih, bhh, out);
}

// round 15
// speedup vs baseline: 1.0188x; 1.0008x over previous
#include <cuda_runtime.h>
#include <cuda_bf16.h>

#define NH  4096
#define DIN 4096

// One block per output index j. 7 warps = 7 full-row dot products (16KB streams):
//   w0: Wih[j]      . x     w1: Whh[j]      . h      (i gate)
//   w2: Wih[nh+j]   . x     w3: Whh[nh+j]   . h      (f gate)
//   w4: Wih[2nh+j]  . x     w5: Whh[2nh+j]  . h      (g gate)
//   w6: Whh[3nh+j]  . h                              (o gate; x-part REUSES w4,
//                                                     reference sets Wio = Wig slice)
// x/h staged in shared memory once per block: vector loads leave the L1tex
// global-load queue entirely, so the read-once weight stream (__ldcs,
// evict-first) owns the LSU/L1tex path and the L2.
__global__ __launch_bounds__(224)
void lstm_cell_kernel(const float* __restrict__ x,
                      const float* __restrict__ h,
                      const float* __restrict__ c,
                      const float* __restrict__ Wih,
                      const float* __restrict__ Whh,
                      const float* __restrict__ bih,
                      const float* __restrict__ bhh,
                      float* __restrict__ out)
{
    const int j    = blockIdx.x;
    const int wid  = threadIdx.x >> 5;
    const int lane = threadIdx.x & 31;

    __shared__ float4 svec[2048];     // [0:1024) = x, [1024:2048) = h  (32 KB)
    __shared__ float  partial[7];

    // Cooperative vector staging: 2048 float4s across 224 threads.
    {
        const float4* __restrict__ xr = reinterpret_cast<const float4*>(x);
        const float4* __restrict__ hr = reinterpret_cast<const float4*>(h);
        for (int i = threadIdx.x; i < 1024; i += 224) {
            svec[i]        = __ldg(&xr[i]);
            svec[i + 1024] = __ldg(&hr[i]);
        }
    }
    __syncthreads();

    // Branchless per-warp dot-product selection.
    const int use_h_tab[7] = {0, 1, 0, 1, 0, 1, 1};
    const int gate_tab [7] = {0, 0, 1, 1, 2, 2, 3};
    const int use_h = use_h_tab[wid];
    const int gate  = gate_tab[wid];

    const float* W  = use_h ? Whh : Wih;
    const long  row = (long)gate * NH + j;

    const float4* __restrict__ Wr = reinterpret_cast<const float4*>(W + row * (long)DIN);
    const float4* vr = svec + use_h * 1024;   // smem operand

    // 1024 float4 per row / 32 lanes = 32 float4 per lane.
    // 4 independent accumulators + batched weight loads -> DRAM MLP;
    // vector operand comes from conflict-free LDS.128.
    float a0 = 0.f, a1 = 0.f, a2 = 0.f, a3 = 0.f;
    #pragma unroll
    for (int it = 0; it < 8; ++it) {
        const int base = it * 128 + lane;           // stride 32 between the 4 loads below
        float4 w0 = __ldcs(&Wr[base]);        float4 x0 = vr[base];
        float4 w1 = __ldcs(&Wr[base + 32]);   float4 x1 = vr[base + 32];
        float4 w2 = __ldcs(&Wr[base + 64]);   float4 x2 = vr[base + 64];
        float4 w3 = __ldcs(&Wr[base + 96]);   float4 x3 = vr[base + 96];
        a0 += w0.x*x0.x + w0.y*x0.y + w0.z*x0.z + w0.w*x0.w;
        a1 += w1.x*x1.x + w1.y*x1.y + w1.z*x1.z + w1.w*x1.w;
        a2 += w2.x*x2.x + w2.y*x2.y + w2.z*x2.z + w2.w*x2.w;
        a3 += w3.x*x3.x + w3.y*x3.y + w3.z*x3.z + w3.w*x3.w;
    }
    float acc = (a0 + a1) + (a2 + a3);

    // Warp tree-reduce.
    #pragma unroll
    for (int off = 16; off > 0; off >>= 1)
        acc += __shfl_down_sync(0xffffffffu, acc, off);

    if (lane == 0) partial[wid] = acc;
    __syncthreads();

    if (threadIdx.x == 0) {
        const float ai = partial[0] + partial[1] + __ldg(&bih[j])        + __ldg(&bhh[j]);
        const float af = partial[2] + partial[3] + __ldg(&bih[NH + j])   + __ldg(&bhh[NH + j]);
        const float ag = partial[4] + partial[5] + __ldg(&bih[2*NH + j]) + __ldg(&bhh[2*NH + j]);
        // o gate: x-part = g gate's x-dot (reference's Wio slice aliases Wig)
        const float ao = partial[4] + partial[6] + __ldg(&bih[3*NH + j]) + __ldg(&bhh[3*NH + j]);

        const float it_ = 1.f / (1.f + __expf(-ai));
        const float ft_ = 1.f / (1.f + __expf(-af));
        const float gt_ = tanhf(ag);
        const float ot_ = 1.f / (1.f + __expf(-ao));
        const float ct_ = ft_ * __ldg(&c[j]) + it_ * gt_;
        const float ht_ = ot_ * tanhf(ct_);

        out[j         ] = it_;
        out[NH   + j  ] = ft_;
        out[2*NH + j  ] = gt_;
        out[3*NH + j  ] = ot_;
        out[4*NH + j  ] = ct_;
        out[5*NH + j  ] = ht_;
    }
}

extern "C" void kernel_launch(void* const* d_in, const int* in_sizes, int n_in,
                              void* d_out, int out_size)
{
    const float* x   = (const float*)d_in[0];
    const float* h   = (const float*)d_in[1];
    const float* c   = (const float*)d_in[2];
    const float* Wih = (const float*)d_in[3];
    const float* Whh = (const float*)d_in[4];
    const float* bih = (const float*)d_in[5];
    const float* bhh = (const float*)d_in[6];
    float* out = (float*)d_out;

    lstm_cell_kernel<<<NH, 224>>>(x, h, c, Wih, Whh, bih, bhh, out);
}

// round 16
// speedup vs baseline: 1.0379x; 1.0188x over previous
#include <cuda_runtime.h>
#include <cuda_bf16.h>

#define NH  4096
#define DIN 4096

// One block per output index j. 7 warps = 7 full-row dot products (16KB streams):
//   w0: Wih[j]      . x     w1: Whh[j]      . h      (i gate)
//   w2: Wih[nh+j]   . x     w3: Whh[nh+j]   . h      (f gate)
//   w4: Wih[2nh+j]  . x     w5: Whh[2nh+j]  . h      (g gate)
//   w6: Whh[3nh+j]  . h                              (o gate; x-part REUSES w4,
//                                                     reference sets Wio = Wig slice)
// Weight stream: ld.global.nc.cs (non-coherent path + evict-first streaming) --
// read-once data stays out of L2/L1 residency; x/h remain cached.
// Effective BW of this shape measured at 6.28 TB/s ~= the path-independent LTS
// cap (~6300 B/cyc), i.e. ~99.5% of the reachable floor (448 MiB / 6.3 TB/s).

__device__ __forceinline__ float4 ldg_nc_cs(const float4* p) {
    float4 r;
    asm volatile("ld.global.nc.cs.v4.f32 {%0,%1,%2,%3}, [%4];"
                 : "=f"(r.x), "=f"(r.y), "=f"(r.z), "=f"(r.w)
                 : "l"(p));
    return r;
}

__global__ __launch_bounds__(224)
void lstm_cell_kernel(const float* __restrict__ x,
                      const float* __restrict__ h,
                      const float* __restrict__ c,
                      const float* __restrict__ Wih,
                      const float* __restrict__ Whh,
                      const float* __restrict__ bih,
                      const float* __restrict__ bhh,
                      float* __restrict__ out)
{
    const int j    = blockIdx.x;
    const int wid  = threadIdx.x >> 5;
    const int lane = threadIdx.x & 31;

    __shared__ float partial[7];

    // Branchless per-warp dot-product selection.
    // use_h[w]: 0 -> (Wih, x), 1 -> (Whh, h).  gate[w]: row block multiplier.
    const int use_h_tab[7] = {0, 1, 0, 1, 0, 1, 1};
    const int gate_tab [7] = {0, 0, 1, 1, 2, 2, 3};
    const int use_h = use_h_tab[wid];
    const int gate  = gate_tab[wid];

    const float* W = use_h ? Whh : Wih;
    const float* v = use_h ? h   : x;
    const long  row = (long)gate * NH + j;

    const float4* __restrict__ Wr = reinterpret_cast<const float4*>(W + row * (long)DIN);
    const float4* __restrict__ vr = reinterpret_cast<const float4*>(v);

    // 1024 float4 per row / 32 lanes = 32 float4 per lane.
    // 4 independent accumulators + batched loads -> MLP for DRAM latency hiding.
    float a0 = 0.f, a1 = 0.f, a2 = 0.f, a3 = 0.f;
    #pragma unroll
    for (int it = 0; it < 8; ++it) {
        const int base = it * 128 + lane;           // stride 32 between the 4 loads below
        float4 w0 = ldg_nc_cs(&Wr[base]);        float4 x0 = vr[base];
        float4 w1 = ldg_nc_cs(&Wr[base + 32]);   float4 x1 = vr[base + 32];
        float4 w2 = ldg_nc_cs(&Wr[base + 64]);   float4 x2 = vr[base + 64];
        float4 w3 = ldg_nc_cs(&Wr[base + 96]);   float4 x3 = vr[base + 96];
        a0 += w0.x*x0.x + w0.y*x0.y + w0.z*x0.z + w0.w*x0.w;
        a1 += w1.x*x1.x + w1.y*x1.y + w1.z*x1.z + w1.w*x1.w;
        a2 += w2.x*x2.x + w2.y*x2.y + w2.z*x2.z + w2.w*x2.w;
        a3 += w3.x*x3.x + w3.y*x3.y + w3.z*x3.z + w3.w*x3.w;
    }
    float acc = (a0 + a1) + (a2 + a3);

    // Warp tree-reduce.
    #pragma unroll
    for (int off = 16; off > 0; off >>= 1)
        acc += __shfl_down_sync(0xffffffffu, acc, off);

    if (lane == 0) partial[wid] = acc;
    __syncthreads();

    if (threadIdx.x == 0) {
        const float ai = partial[0] + partial[1] + __ldg(&bih[j])        + __ldg(&bhh[j]);
        const float af = partial[2] + partial[3] + __ldg(&bih[NH + j])   + __ldg(&bhh[NH + j]);
        const float ag = partial[4] + partial[5] + __ldg(&bih[2*NH + j]) + __ldg(&bhh[2*NH + j]);
        // o gate: x-part = g gate's x-dot (reference's Wio slice aliases Wig)
        const float ao = partial[4] + partial[6] + __ldg(&bih[3*NH + j]) + __ldg(&bhh[3*NH + j]);

        const float it_ = 1.f / (1.f + __expf(-ai));
        const float ft_ = 1.f / (1.f + __expf(-af));
        const float gt_ = tanhf(ag);
        const float ot_ = 1.f / (1.f + __expf(-ao));
        const float ct_ = ft_ * __ldg(&c[j]) + it_ * gt_;
        const float ht_ = ot_ * tanhf(ct_);

        out[j         ] = it_;
        out[NH   + j  ] = ft_;
        out[2*NH + j  ] = gt_;
        out[3*NH + j  ] = ot_;
        out[4*NH + j  ] = ct_;
        out[5*NH + j  ] = ht_;
    }
}

extern "C" void kernel_launch(void* const* d_in, const int* in_sizes, int n_in,
                              void* d_out, int out_size)
{
    const float* x   = (const float*)d_in[0];
    const float* h   = (const float*)d_in[1];
    const float* c   = (const float*)d_in[2];
    const float* Wih = (const float*)d_in[3];
    const float* Whh = (const float*)d_in[4];
    const float* bih = (const float*)d_in[5];
    const float* bhh = (const float*)d_in[6];
    float* out = (float*)d_out;

    lstm_cell_kernel<<<NH, 224>>>(x, h, c, Wih, Whh, bih, bhh, out);
}